// round 6
// baseline (speedup 1.0000x reference)
#include <cuda_runtime.h>
#include <math.h>

// Problem constants
#define VOCAB 50257
#define EMB   16
#define BS    8
#define MCW   512
#define NTOK  (BS * MCW)      // 4096 tokens

typedef unsigned long long ull;

// Scratch (device globals: allocation-free)
__device__ float g_Q[NTOK * EMB];
__device__ float g_K[NTOK * EMB];
__device__ float g_V[NTOK * EMB];
__device__ float g_Wt[BS * MCW * MCW];   // g_Wt[b][k][q] : softmaxed weight (b,q,k), k-major
__device__ float g_out[NTOK * EMB];

// ---------------------------------------------------------------------------
// packed fp32x2 helpers operating on 64-bit registers directly (no MOVs)
// ---------------------------------------------------------------------------
__device__ __forceinline__ ull fma2u(ull a, ull b, ull c) {
    ull d;
    asm("fma.rn.f32x2 %0, %1, %2, %3;" : "=l"(d) : "l"(a), "l"(b), "l"(c));
    return d;
}

__device__ __forceinline__ ull add2u(ull a, ull b) {
    ull d;
    asm("add.rn.f32x2 %0, %1, %2;" : "=l"(d) : "l"(a), "l"(b));
    return d;
}

__device__ __forceinline__ ull pk(float lo, float hi) {
    return ((ull)__float_as_uint(hi) << 32) | (ull)__float_as_uint(lo);
}
__device__ __forceinline__ float lo32(ull v) { return __uint_as_float((unsigned)v); }
__device__ __forceinline__ float hi32(ull v) { return __uint_as_float((unsigned)(v >> 32)); }

// ---------------------------------------------------------------------------
// Kernel 1: embedding gather + Q/K/V projections
// ---------------------------------------------------------------------------
__global__ void qkv_kernel(const int* __restrict__ x,
                           const float* __restrict__ emb_table,
                           const float* __restrict__ Wq, const float* __restrict__ bq,
                           const float* __restrict__ Wk, const float* __restrict__ bk,
                           const float* __restrict__ Wv, const float* __restrict__ bv) {
    __shared__ float semb[16][EMB];
    int lt = threadIdx.x >> 4;     // local token 0..15
    int e  = threadIdx.x & 15;     // output dim
    int tok = blockIdx.x * 16 + lt;
    int id = x[tok];
    semb[lt][e] = emb_table[id * EMB + e];
    __syncthreads();

    float q = bq[e], k = bk[e], v = bv[e];
#pragma unroll
    for (int j = 0; j < EMB; ++j) {
        float ej = semb[lt][j];
        q = fmaf(Wq[e * EMB + j], ej, q);
        k = fmaf(Wk[e * EMB + j], ej, k);
        v = fmaf(Wv[e * EMB + j], ej, v);
    }
    g_Q[tok * EMB + e] = q;
    g_K[tok * EMB + e] = k;
    g_V[tok * EMB + e] = v;
}

// ---------------------------------------------------------------------------
// Block reduction over 512 threads (16 warps)
// ---------------------------------------------------------------------------
__device__ __forceinline__ float block_reduce(float v, bool do_max, float* sred, int tid) {
#pragma unroll
    for (int o = 16; o > 0; o >>= 1) {
        float s = __shfl_xor_sync(0xffffffffu, v, o);
        v = do_max ? fmaxf(v, s) : (v + s);
    }
    if ((tid & 31) == 0) sred[tid >> 5] = v;
    __syncthreads();
    if (tid < 32) {
        float t = (tid < 16) ? sred[tid] : (do_max ? -INFINITY : 0.0f);
#pragma unroll
        for (int o = 8; o > 0; o >>= 1) {
            float s = __shfl_xor_sync(0xffffffffu, t, o);
            t = do_max ? fmaxf(t, s) : (t + s);
        }
        if (tid == 0) sred[0] = t;
    }
    __syncthreads();
    float r = sred[0];
    __syncthreads();   // protect sred reuse
    return r;
}

// ---------------------------------------------------------------------------
// Kernel 2: scores + mask + zero->-inf quirk + softmax over QUERY axis
// grid: (MCW/8, BS); block: 512 threads (q). writes g_Wt[b][k][q]
// ---------------------------------------------------------------------------
__global__ void attn_weights_kernel() {
    int kc0 = blockIdx.x * 8;
    int b   = blockIdx.y;
    int tid = threadIdx.x;   // q index

    __shared__ float sK[8][EMB];
    __shared__ float sred[16];

    const float4* qrow = reinterpret_cast<const float4*>(g_Q + (b * MCW + tid) * EMB);
    float4 q0 = qrow[0], q1 = qrow[1], q2 = qrow[2], q3 = qrow[3];

    if (tid < 8 * EMB) {
        sK[tid >> 4][tid & 15] = g_K[(b * MCW + kc0 + (tid >> 4)) * EMB + (tid & 15)];
    }
    __syncthreads();

#pragma unroll
    for (int kc = 0; kc < 8; ++kc) {
        int kcol = kc0 + kc;
        const float* kv = sK[kc];
        float s = 0.0f;
        s = fmaf(q0.x, kv[0],  s); s = fmaf(q0.y, kv[1],  s);
        s = fmaf(q0.z, kv[2],  s); s = fmaf(q0.w, kv[3],  s);
        s = fmaf(q1.x, kv[4],  s); s = fmaf(q1.y, kv[5],  s);
        s = fmaf(q1.z, kv[6],  s); s = fmaf(q1.w, kv[7],  s);
        s = fmaf(q2.x, kv[8],  s); s = fmaf(q2.y, kv[9],  s);
        s = fmaf(q2.z, kv[10], s); s = fmaf(q2.w, kv[11], s);
        s = fmaf(q3.x, kv[12], s); s = fmaf(q3.y, kv[13], s);
        s = fmaf(q3.z, kv[14], s); s = fmaf(q3.w, kv[15], s);

        // mask: keep only k <= q ; quirk: exact-zero scores -> -inf
        float val = (kcol <= tid && s != 0.0f) ? s : -INFINITY;

        float m = block_reduce(val, true, sred, tid);
        float p = __expf(val - m);
        float sum = block_reduce(p, false, sred, tid);
        float w = p / sum;

        g_Wt[((size_t)(b * MCW + kcol)) * MCW + tid] = w;   // coalesced over q
    }
}

// ---------------------------------------------------------------------------
// Kernel 3: out[b,w,e] = sum_p Wt[b][p][w] * V[b,p,e]
// ---------------------------------------------------------------------------
__global__ void attn_out_kernel() {
    int b  = blockIdx.y;
    int w  = blockIdx.x * 16 + (threadIdx.x & 15);
    int e  = threadIdx.x >> 4;

    __shared__ float sV[MCW * EMB];   // 32 KB
    const float* Vb = g_V + b * MCW * EMB;
    for (int i = threadIdx.x; i < MCW * EMB; i += 256) sV[i] = Vb[i];
    __syncthreads();

    const float* Wtb = g_Wt + (size_t)b * MCW * MCW;
    float acc = 0.0f;
#pragma unroll 8
    for (int p = 0; p < MCW; ++p)
        acc = fmaf(Wtb[p * MCW + w], sV[p * EMB + e], acc);

    g_out[(b * MCW + w) * EMB + e] = acc;
}

// ---------------------------------------------------------------------------
// Kernel 4: logits[t, v] = dot(out[t,:], Wl[v,:]) + bl[v]
// Thread owns vocab rows {v, v+256, v+512, v+768}, v = vbase + tid:
//   pair0 = (v, v+256), pair1 = (v+512, v+768) packed in f32x2.
// -> all 4 stores per token are lane-consecutive (fully coalesced STG.32).
// Token vectors staged in smem as dup-pairs (t[k],t[k]) in 64-bit words;
// inner loop = 8 LDS.128 + 32 FFMA2 + 2 ADD2, zero MOVs ("l" constraints).
// ---------------------------------------------------------------------------
#define TC  256      // tokens per block
#define VB  1024     // vocab per block (256 threads * 4 rows)

__global__ void __launch_bounds__(256, 2)
logits_kernel(const float* __restrict__ Wl, const float* __restrict__ bl,
              float* __restrict__ logits) {
    // stok[t*8 + j] = ( dup(out[t][2j]), dup(out[t][2j+1]) )  : 32 KB
    __shared__ ulonglong2 stok[TC * 8];

    int tid   = threadIdx.x;
    int t0    = blockIdx.y * TC;
    int vbase = blockIdx.x * VB;

    // stage dup-pair token vectors
    const float2* src = reinterpret_cast<const float2*>(g_out + t0 * EMB);
    for (int i = tid; i < TC * 8; i += 256) {
        float2 v = src[i];
        stok[i] = make_ulonglong2(pk(v.x, v.x), pk(v.y, v.y));
    }

    // this thread's 4 vocab rows
    int v0 = vbase + tid;          // row A
    int v1 = v0 + 256;             // row B   (pair0 = A,B)
    int v2 = v0 + 512;             // row C
    int v3 = v0 + 768;             // row D   (pair1 = C,D)

    bool a0 = (v0 < VOCAB), a1 = (v1 < VOCAB);
    bool c0 = (v2 < VOCAB), c1 = (v3 < VOCAB);

    ull wl0[EMB], wl1[EMB];
#pragma unroll
    for (int k = 0; k < EMB; ++k) {
        wl0[k] = pk(a0 ? Wl[v0 * EMB + k] : 0.0f,
                    a1 ? Wl[v1 * EMB + k] : 0.0f);
        wl1[k] = pk(c0 ? Wl[v2 * EMB + k] : 0.0f,
                    c1 ? Wl[v3 * EMB + k] : 0.0f);
    }
    ull bias0 = pk(a0 ? bl[v0] : 0.0f, a1 ? bl[v1] : 0.0f);
    ull bias1 = pk(c0 ? bl[v2] : 0.0f, c1 ? bl[v3] : 0.0f);

    __syncthreads();

    for (int t = 0; t < TC; ++t) {
        const ulonglong2* tk = stok + t * 8;
        // 4 independent FFMA2 chains, depth 8
        ull p00 = bias0, p01 = 0ull;
        ull p10 = bias1, p11 = 0ull;
#pragma unroll
        for (int j = 0; j < 8; ++j) {
            ulonglong2 tv = tk[j];      // .x = dup(t[2j]), .y = dup(t[2j+1])
            p00 = fma2u(wl0[2 * j],     tv.x, p00);
            p01 = fma2u(wl0[2 * j + 1], tv.y, p01);
            p10 = fma2u(wl1[2 * j],     tv.x, p10);
            p11 = fma2u(wl1[2 * j + 1], tv.y, p11);
        }
        ull acc0 = add2u(p00, p01);     // (logit[v0], logit[v1])
        ull acc1 = add2u(p10, p11);     // (logit[v2], logit[v3])

        size_t base = (size_t)(t0 + t) * VOCAB;
        // lane-consecutive -> fully coalesced
        if (a0) logits[base + v0] = lo32(acc0);
        if (a1) logits[base + v1] = hi32(acc0);
        if (c0) logits[base + v2] = lo32(acc1);
        if (c1) logits[base + v3] = hi32(acc1);
    }
}

// ---------------------------------------------------------------------------
extern "C" void kernel_launch(void* const* d_in, const int* in_sizes, int n_in,
                              void* d_out, int out_size) {
    const int*   x         = (const int*)  d_in[0];
    const float* emb_table = (const float*)d_in[1];
    const float* Wq        = (const float*)d_in[2];
    const float* bq        = (const float*)d_in[3];
    const float* Wk        = (const float*)d_in[4];
    const float* bk        = (const float*)d_in[5];
    const float* Wv        = (const float*)d_in[6];
    const float* bv        = (const float*)d_in[7];
    const float* Wl        = (const float*)d_in[8];
    const float* bl        = (const float*)d_in[9];
    float* logits          = (float*)d_out;

    qkv_kernel<<<NTOK / 16, 256>>>(x, emb_table, Wq, bq, Wk, bk, Wv, bv);

    dim3 g2(MCW / 8, BS);
    attn_weights_kernel<<<g2, MCW>>>();

    dim3 g3(MCW / 16, BS);
    attn_out_kernel<<<g3, 256>>>();

    dim3 g4((VOCAB + VB - 1) / VB, NTOK / TC);
    logits_kernel<<<g4, 256>>>(Wl, bl, logits);
}

// round 7
// speedup vs baseline: 2.7002x; 2.7002x over previous
#include <cuda_runtime.h>
#include <math.h>

// Problem constants
#define VOCAB 50257
#define EMB   16
#define BS    8
#define MCW   512
#define NTOK  (BS * MCW)      // 4096 tokens

// Scratch (device globals: allocation-free)
__device__ float g_Q[NTOK * EMB];
__device__ float g_K[NTOK * EMB];
__device__ float g_V[NTOK * EMB];
__device__ float g_Wt[BS * MCW * MCW];   // g_Wt[b][k][q] : softmaxed weight (b,q,k), k-major
__device__ float g_out[NTOK * EMB];

// ---------------------------------------------------------------------------
// packed fp32x2 helpers (float2 constraints — proven no-spill form from R4)
// ---------------------------------------------------------------------------
__device__ __forceinline__ float2 fma2(float2 a, float2 b, float2 c) {
    float2 d;
    asm("{\n\t"
        ".reg .b64 ra, rb, rc, rd;\n\t"
        "mov.b64 ra, {%2, %3};\n\t"
        "mov.b64 rb, {%4, %5};\n\t"
        "mov.b64 rc, {%6, %7};\n\t"
        "fma.rn.f32x2 rd, ra, rb, rc;\n\t"
        "mov.b64 {%0, %1}, rd;\n\t"
        "}"
        : "=f"(d.x), "=f"(d.y)
        : "f"(a.x), "f"(a.y), "f"(b.x), "f"(b.y), "f"(c.x), "f"(c.y));
    return d;
}

__device__ __forceinline__ float2 add2(float2 a, float2 b) {
    float2 d;
    asm("{\n\t"
        ".reg .b64 ra, rb, rd;\n\t"
        "mov.b64 ra, {%2, %3};\n\t"
        "mov.b64 rb, {%4, %5};\n\t"
        "add.rn.f32x2 rd, ra, rb;\n\t"
        "mov.b64 {%0, %1}, rd;\n\t"
        "}"
        : "=f"(d.x), "=f"(d.y)
        : "f"(a.x), "f"(a.y), "f"(b.x), "f"(b.y));
    return d;
}

// ---------------------------------------------------------------------------
// Kernel 1: embedding gather + Q/K/V projections
// ---------------------------------------------------------------------------
__global__ void qkv_kernel(const int* __restrict__ x,
                           const float* __restrict__ emb_table,
                           const float* __restrict__ Wq, const float* __restrict__ bq,
                           const float* __restrict__ Wk, const float* __restrict__ bk,
                           const float* __restrict__ Wv, const float* __restrict__ bv) {
    __shared__ float semb[16][EMB];
    int lt = threadIdx.x >> 4;     // local token 0..15
    int e  = threadIdx.x & 15;     // output dim
    int tok = blockIdx.x * 16 + lt;
    int id = x[tok];
    semb[lt][e] = emb_table[id * EMB + e];
    __syncthreads();

    float q = bq[e], k = bk[e], v = bv[e];
#pragma unroll
    for (int j = 0; j < EMB; ++j) {
        float ej = semb[lt][j];
        q = fmaf(Wq[e * EMB + j], ej, q);
        k = fmaf(Wk[e * EMB + j], ej, k);
        v = fmaf(Wv[e * EMB + j], ej, v);
    }
    g_Q[tok * EMB + e] = q;
    g_K[tok * EMB + e] = k;
    g_V[tok * EMB + e] = v;
}

// ---------------------------------------------------------------------------
// Block reduction over 512 threads (16 warps)
// ---------------------------------------------------------------------------
__device__ __forceinline__ float block_reduce(float v, bool do_max, float* sred, int tid) {
#pragma unroll
    for (int o = 16; o > 0; o >>= 1) {
        float s = __shfl_xor_sync(0xffffffffu, v, o);
        v = do_max ? fmaxf(v, s) : (v + s);
    }
    if ((tid & 31) == 0) sred[tid >> 5] = v;
    __syncthreads();
    if (tid < 32) {
        float t = (tid < 16) ? sred[tid] : (do_max ? -INFINITY : 0.0f);
#pragma unroll
        for (int o = 8; o > 0; o >>= 1) {
            float s = __shfl_xor_sync(0xffffffffu, t, o);
            t = do_max ? fmaxf(t, s) : (t + s);
        }
        if (tid == 0) sred[0] = t;
    }
    __syncthreads();
    float r = sred[0];
    __syncthreads();   // protect sred reuse
    return r;
}

// ---------------------------------------------------------------------------
// Kernel 2: scores + mask + zero->-inf quirk + softmax over QUERY axis
// grid: (MCW/8, BS); block: 512 threads (q). writes g_Wt[b][k][q]
// ---------------------------------------------------------------------------
__global__ void attn_weights_kernel() {
    int kc0 = blockIdx.x * 8;
    int b   = blockIdx.y;
    int tid = threadIdx.x;   // q index

    __shared__ float sK[8][EMB];
    __shared__ float sred[16];

    const float4* qrow = reinterpret_cast<const float4*>(g_Q + (b * MCW + tid) * EMB);
    float4 q0 = qrow[0], q1 = qrow[1], q2 = qrow[2], q3 = qrow[3];

    if (tid < 8 * EMB) {
        sK[tid >> 4][tid & 15] = g_K[(b * MCW + kc0 + (tid >> 4)) * EMB + (tid & 15)];
    }
    __syncthreads();

#pragma unroll
    for (int kc = 0; kc < 8; ++kc) {
        int kcol = kc0 + kc;
        const float* kv = sK[kc];
        float s = 0.0f;
        s = fmaf(q0.x, kv[0],  s); s = fmaf(q0.y, kv[1],  s);
        s = fmaf(q0.z, kv[2],  s); s = fmaf(q0.w, kv[3],  s);
        s = fmaf(q1.x, kv[4],  s); s = fmaf(q1.y, kv[5],  s);
        s = fmaf(q1.z, kv[6],  s); s = fmaf(q1.w, kv[7],  s);
        s = fmaf(q2.x, kv[8],  s); s = fmaf(q2.y, kv[9],  s);
        s = fmaf(q2.z, kv[10], s); s = fmaf(q2.w, kv[11], s);
        s = fmaf(q3.x, kv[12], s); s = fmaf(q3.y, kv[13], s);
        s = fmaf(q3.z, kv[14], s); s = fmaf(q3.w, kv[15], s);

        // mask: keep only k <= q ; quirk: exact-zero scores -> -inf
        float val = (kcol <= tid && s != 0.0f) ? s : -INFINITY;

        float m = block_reduce(val, true, sred, tid);
        float p = __expf(val - m);
        float sum = block_reduce(p, false, sred, tid);
        float w = p / sum;

        g_Wt[((size_t)(b * MCW + kcol)) * MCW + tid] = w;   // coalesced over q
    }
}

// ---------------------------------------------------------------------------
// Kernel 3: out[b,w,e] = sum_p Wt[b][p][w] * V[b,p,e]
// ---------------------------------------------------------------------------
__global__ void attn_out_kernel() {
    int b  = blockIdx.y;
    int w  = blockIdx.x * 16 + (threadIdx.x & 15);
    int e  = threadIdx.x >> 4;

    __shared__ float sV[MCW * EMB];   // 32 KB
    const float* Vb = g_V + b * MCW * EMB;
    for (int i = threadIdx.x; i < MCW * EMB; i += 256) sV[i] = Vb[i];
    __syncthreads();

    const float* Wtb = g_Wt + (size_t)b * MCW * MCW;
    float acc = 0.0f;
#pragma unroll 8
    for (int p = 0; p < MCW; ++p)
        acc = fmaf(Wtb[p * MCW + w], sV[p * EMB + e], acc);

    g_out[(b * MCW + w) * EMB + e] = acc;
}

// ---------------------------------------------------------------------------
// Kernel 4: logits[t, v] = dot(out[t,:], Wl[v,:]) + bl[v]
// R4 structure (dup-quad smem, float2 fma2, 4 chains depth 8) with:
//  - coalesced row mapping: thread owns {v, v+256, v+512, v+768}, v=vbase+tid
//    -> all 4 STG.32 per token are lane-consecutive (4 store wavefronts not 8)
//  - token loop unrolled x2 so next token's LDS are hoisted above current FMAs
// ---------------------------------------------------------------------------
#define TC  256      // tokens per block
#define VB  1024     // vocab per block (256 threads * 4 rows)

__global__ void __launch_bounds__(256, 2)
logits_kernel(const float* __restrict__ Wl, const float* __restrict__ bl,
              float* __restrict__ logits) {
    __shared__ float4 stok[TC * 8];   // 32 KB : stok[t*8+j] = (t[2j],t[2j],t[2j+1],t[2j+1])

    int tid   = threadIdx.x;
    int t0    = blockIdx.y * TC;
    int vbase = blockIdx.x * VB;

    // stage dup-quad token vectors
    const float2* src = reinterpret_cast<const float2*>(g_out + t0 * EMB);
    for (int i = tid; i < TC * 8; i += 256) {
        float2 v = src[i];
        stok[i] = make_float4(v.x, v.x, v.y, v.y);
    }

    // this thread's 4 vocab rows (lane-consecutive within each group of 256)
    int v0 = vbase + tid;          // row A
    int v1 = v0 + 256;             // row B   (pair0 = A,B)
    int v2 = v0 + 512;             // row C
    int v3 = v0 + 768;             // row D   (pair1 = C,D)

    bool a0 = (v0 < VOCAB), a1 = (v1 < VOCAB);
    bool c0 = (v2 < VOCAB), c1 = (v3 < VOCAB);

    float2 wl0[EMB], wl1[EMB];
#pragma unroll
    for (int k = 0; k < EMB; ++k) {
        wl0[k] = make_float2(a0 ? Wl[v0 * EMB + k] : 0.0f,
                             a1 ? Wl[v1 * EMB + k] : 0.0f);
        wl1[k] = make_float2(c0 ? Wl[v2 * EMB + k] : 0.0f,
                             c1 ? Wl[v3 * EMB + k] : 0.0f);
    }
    float2 b0 = make_float2(a0 ? bl[v0] : 0.0f, a1 ? bl[v1] : 0.0f);
    float2 b1 = make_float2(c0 ? bl[v2] : 0.0f, c1 ? bl[v3] : 0.0f);

    __syncthreads();

#pragma unroll 2
    for (int t = 0; t < TC; ++t) {
        const float4* tk = stok + t * 8;
        // 4 independent chains, depth 8
        float2 p00 = b0;
        float2 p01 = make_float2(0.0f, 0.0f);
        float2 p10 = b1;
        float2 p11 = make_float2(0.0f, 0.0f);
#pragma unroll
        for (int j = 0; j < 8; ++j) {
            float4 tv = tk[j];
            float2 ta = make_float2(tv.x, tv.y);   // dup of t[2j]
            float2 tb = make_float2(tv.z, tv.w);   // dup of t[2j+1]
            p00 = fma2(wl0[2 * j],     ta, p00);
            p01 = fma2(wl0[2 * j + 1], tb, p01);
            p10 = fma2(wl1[2 * j],     ta, p10);
            p11 = fma2(wl1[2 * j + 1], tb, p11);
        }
        float2 acc0 = add2(p00, p01);   // (logit[v0], logit[v1])
        float2 acc1 = add2(p10, p11);   // (logit[v2], logit[v3])

        size_t base = (size_t)(t0 + t) * VOCAB;
        // lane-consecutive -> fully coalesced STG.32
        if (a0) logits[base + v0] = acc0.x;
        if (a1) logits[base + v1] = acc0.y;
        if (c0) logits[base + v2] = acc1.x;
        if (c1) logits[base + v3] = acc1.y;
    }
}

// ---------------------------------------------------------------------------
extern "C" void kernel_launch(void* const* d_in, const int* in_sizes, int n_in,
                              void* d_out, int out_size) {
    const int*   x         = (const int*)  d_in[0];
    const float* emb_table = (const float*)d_in[1];
    const float* Wq        = (const float*)d_in[2];
    const float* bq        = (const float*)d_in[3];
    const float* Wk        = (const float*)d_in[4];
    const float* bk        = (const float*)d_in[5];
    const float* Wv        = (const float*)d_in[6];
    const float* bv        = (const float*)d_in[7];
    const float* Wl        = (const float*)d_in[8];
    const float* bl        = (const float*)d_in[9];
    float* logits          = (float*)d_out;

    qkv_kernel<<<NTOK / 16, 256>>>(x, emb_table, Wq, bq, Wk, bk, Wv, bv);

    dim3 g2(MCW / 8, BS);
    attn_weights_kernel<<<g2, MCW>>>();

    dim3 g3(MCW / 16, BS);
    attn_out_kernel<<<g3, 256>>>();

    dim3 g4((VOCAB + VB - 1) / VB, NTOK / TC);
    logits_kernel<<<g4, 256>>>(Wl, bl, logits);
}